// round 1
// baseline (speedup 1.0000x reference)
#include <cuda_runtime.h>

#define B_TOTAL 32768
#define D   256
#define H1  512
#define H2  256
#define E   16
#define O   64
#define BT  32
#define THREADS 512
#define XPAD 36   // padded row stride (floats), keeps 16B alignment, avoids bank conflicts

// SMEM layout (floats):
//   x_t   [D][XPAD]    : x tile transposed, x_t[d][b]
//   h1t   [H1][XPAD]   : relu(h1) transposed, h1t[h][b]
//   h2t   [H2][XPAD]   : relu(h2) transposed, h2t[k][b]
//   gates [BT][E]
#define SMEM_FLOATS (D*XPAD + H1*XPAD + H2*XPAD + BT*E)

__global__ __launch_bounds__(THREADS, 1)
void moe_yts_fused_kernel(const float* __restrict__ x,
                          const float* __restrict__ gate_w,
                          const float* __restrict__ gate_b,
                          const float* __restrict__ W1,
                          const float* __restrict__ b1,
                          const float* __restrict__ W2,
                          const float* __restrict__ b2,
                          const float* __restrict__ W3,
                          const float* __restrict__ b3,
                          const float* __restrict__ head_w,
                          const float* __restrict__ head_b,
                          float* __restrict__ out)
{
    extern __shared__ float smem[];
    float* x_t     = smem;                  // [D][XPAD]
    float* h1t     = x_t + D * XPAD;        // [H1][XPAD]
    float* h2t     = h1t + H1 * XPAD;       // [H2][XPAD]
    float* gates_s = h2t + H2 * XPAD;       // [BT][E]

    const int t      = threadIdx.x;
    const int b_base = blockIdx.x * BT;

    // ---- Load x tile [BT, D] transposed into SMEM (coalesced float4 reads) ----
    for (int idx = t; idx < BT * (D / 4); idx += THREADS) {
        int row = idx >> 6;        // D/4 = 64 float4 per row
        int c4  = idx & 63;
        float4 v = *(const float4*)(x + (size_t)(b_base + row) * D + c4 * 4);
        x_t[(c4 * 4 + 0) * XPAD + row] = v.x;
        x_t[(c4 * 4 + 1) * XPAD + row] = v.y;
        x_t[(c4 * 4 + 2) * XPAD + row] = v.z;
        x_t[(c4 * 4 + 3) * XPAD + row] = v.w;
    }
    __syncthreads();

    // ---- Gate logits: thread t -> (b = t>>4, e = t&15) ----
    {
        int b = t >> 4;
        int e = t & 15;
        float acc = gate_b[e];
        #pragma unroll 8
        for (int d = 0; d < D; d++)
            acc = fmaf(x_t[d * XPAD + b], gate_w[d * E + e], acc);
        gates_s[b * E + e] = acc;
    }
    __syncthreads();
    // softmax per row (cheap: 32 rows x 16)
    if (t < BT) {
        float* row = gates_s + t * E;
        float m = row[0];
        #pragma unroll
        for (int e = 1; e < E; e++) m = fmaxf(m, row[e]);
        float s = 0.f;
        #pragma unroll
        for (int e = 0; e < E; e++) { float v = expf(row[e] - m); row[e] = v; s += v; }
        float inv = 1.0f / s;
        #pragma unroll
        for (int e = 0; e < E; e++) row[e] *= inv;
    }
    __syncthreads();

    // ---- Per-phase thread roles ----
    const int hg  = t & 127, bgA = t >> 7;    // GEMM1: 128 h-groups x 4 b-groups
    const int h0  = hg * 4,  bA0 = bgA * 8;   //   each thread: 8 b-rows x 4 h-cols
    const int kg  = t & 63,  bgB = t >> 6;    // GEMM2: 64 k-groups x 8 b-groups
    const int k0  = kg * 4,  bB0 = bgB * 4;   //   each thread: 4 b-rows x 4 k-cols
    const int og  = t & 15,  bC  = t >> 4;    // GEMM3: 16 o-groups x 32 b-rows
    const int o0  = og * 4;                   //   each thread: 1 b-row x 4 o-cols

    float fused[4] = {0.f, 0.f, 0.f, 0.f};    // persists across experts

    for (int e = 0; e < E; e++) {
        // ================= GEMM1: h1 = relu(x @ W1[e] + b1[e]) =================
        {
            float acc[8][4];
            #pragma unroll
            for (int i = 0; i < 8; i++)
                #pragma unroll
                for (int j = 0; j < 4; j++) acc[i][j] = 0.f;

            const float* w1p = W1 + (size_t)e * D * H1 + h0;
            #pragma unroll 4
            for (int d = 0; d < D; d++) {
                float4 w  = *(const float4*)(w1p + d * H1);
                float4 xa = *(const float4*)(x_t + d * XPAD + bA0);
                float4 xb = *(const float4*)(x_t + d * XPAD + bA0 + 4);
                float xv[8] = {xa.x, xa.y, xa.z, xa.w, xb.x, xb.y, xb.z, xb.w};
                float wv[4] = {w.x, w.y, w.z, w.w};
                #pragma unroll
                for (int i = 0; i < 8; i++)
                    #pragma unroll
                    for (int j = 0; j < 4; j++)
                        acc[i][j] = fmaf(xv[i], wv[j], acc[i][j]);
            }
            float4 bb = *(const float4*)(b1 + e * H1 + h0);
            float bj[4] = {bb.x, bb.y, bb.z, bb.w};
            #pragma unroll
            for (int j = 0; j < 4; j++) {
                float* dst = h1t + (h0 + j) * XPAD + bA0;
                #pragma unroll
                for (int i = 0; i < 8; i++)
                    dst[i] = fmaxf(acc[i][j] + bj[j], 0.f);
            }
        }
        __syncthreads();

        // ================= GEMM2: h2 = relu(h1 @ W2[e] + b2[e]) ================
        {
            float acc[4][4];
            #pragma unroll
            for (int i = 0; i < 4; i++)
                #pragma unroll
                for (int j = 0; j < 4; j++) acc[i][j] = 0.f;

            const float* w2p = W2 + (size_t)e * H1 * H2 + k0;
            #pragma unroll 4
            for (int h = 0; h < H1; h++) {
                float4 w  = *(const float4*)(w2p + h * H2);
                float4 xa = *(const float4*)(h1t + h * XPAD + bB0);
                float xv[4] = {xa.x, xa.y, xa.z, xa.w};
                float wv[4] = {w.x, w.y, w.z, w.w};
                #pragma unroll
                for (int i = 0; i < 4; i++)
                    #pragma unroll
                    for (int j = 0; j < 4; j++)
                        acc[i][j] = fmaf(xv[i], wv[j], acc[i][j]);
            }
            float4 bb = *(const float4*)(b2 + e * H2 + k0);
            float bj[4] = {bb.x, bb.y, bb.z, bb.w};
            #pragma unroll
            for (int j = 0; j < 4; j++) {
                float* dst = h2t + (k0 + j) * XPAD + bB0;
                #pragma unroll
                for (int i = 0; i < 4; i++)
                    dst[i] = fmaxf(acc[i][j] + bj[j], 0.f);
            }
        }
        __syncthreads();

        // ======= GEMM3: eo = h2 @ W3[e] + b3[e]; fused += gates[b,e] * eo ======
        {
            float a3[4] = {0.f, 0.f, 0.f, 0.f};
            const float* w3p = W3 + (size_t)e * H2 * O + o0;
            #pragma unroll 4
            for (int k = 0; k < H2; k++) {
                float4 w  = *(const float4*)(w3p + k * O);
                float hv  = h2t[k * XPAD + bC];
                a3[0] = fmaf(hv, w.x, a3[0]);
                a3[1] = fmaf(hv, w.y, a3[1]);
                a3[2] = fmaf(hv, w.z, a3[2]);
                a3[3] = fmaf(hv, w.w, a3[3]);
            }
            float4 bb = *(const float4*)(b3 + e * O + o0);
            float g = gates_s[bC * E + e];
            fused[0] = fmaf(g, a3[0] + bb.x, fused[0]);
            fused[1] = fmaf(g, a3[1] + bb.y, fused[1]);
            fused[2] = fmaf(g, a3[2] + bb.z, fused[2]);
            fused[3] = fmaf(g, a3[3] + bb.w, fused[3]);
        }
        __syncthreads();
    }

    // ---- Head: y[b] = sum_o fused[b][o] * head_w[o] + head_b ----
    {
        float4 hw = *(const float4*)(head_w + o0);
        float p = fused[0] * hw.x + fused[1] * hw.y + fused[2] * hw.z + fused[3] * hw.w;
        // reduce over the 16 o-groups; lanes (b even: 0-15, b odd: 16-31)
        #pragma unroll
        for (int off = 8; off >= 1; off >>= 1)
            p += __shfl_xor_sync(0xffffffffu, p, off);
        if (og == 0)
            out[b_base + bC] = p + head_b[0];
    }
}

extern "C" void kernel_launch(void* const* d_in, const int* in_sizes, int n_in,
                              void* d_out, int out_size) {
    const float* x      = (const float*)d_in[0];
    const float* gate_w = (const float*)d_in[1];
    const float* gate_b = (const float*)d_in[2];
    const float* W1     = (const float*)d_in[3];
    const float* b1     = (const float*)d_in[4];
    const float* W2     = (const float*)d_in[5];
    const float* b2     = (const float*)d_in[6];
    const float* W3     = (const float*)d_in[7];
    const float* b3     = (const float*)d_in[8];
    const float* head_w = (const float*)d_in[9];
    const float* head_b = (const float*)d_in[10];
    float* out = (float*)d_out;

    const size_t smem_bytes = (size_t)SMEM_FLOATS * sizeof(float); // 149504 B
    cudaFuncSetAttribute(moe_yts_fused_kernel,
                         cudaFuncAttributeMaxDynamicSharedMemorySize,
                         (int)smem_bytes);

    moe_yts_fused_kernel<<<B_TOTAL / BT, THREADS, smem_bytes>>>(
        x, gate_w, gate_b, W1, b1, W2, b2, W3, b3, head_w, head_b, out);
}